// round 16
// baseline (speedup 1.0000x reference)
#include <cuda_runtime.h>
#include <cuda_fp16.h>
#include <math.h>
#include <stdint.h>

// ---------------------------------------------------------------------------
// Problem constants
// ---------------------------------------------------------------------------
#define M_TOTAL 32768      // B*S
#define K_DIM   512        // H
#define N_DIM   640        // G*V
#define G_NUM   2
#define V_NUM   320
#define DG      128
#define WSCALE  64.0f      // pre-scale on W and bias (argmax-invariant)

// GEMM tiling: BM=BN=64, A through smem (3 buffers), B direct-to-register
#define BM 64
#define BN 64
#define BK 32
#define NKS (K_DIM / BK)        // 16 k-stages
#define A_ST 8192               // A stage bytes: 64 rows x 128B (fp16 h+m)
#define NSTG 3
#define SMEM_BYTES (NSTG * A_ST)    // 24576 (x4 CTAs = 96KB/SM)

// ---------------------------------------------------------------------------
// Device-global scratch
// ---------------------------------------------------------------------------
__device__ uint4 g_asp[(size_t)M_TOTAL * 32 * 4];   // A split: per (m,kb16): h[32B] m[32B]
__device__ uint4 g_bsp[80 * 32 * 32];               // B split, frag-permuted: [ntg][kb][lane]
__device__ unsigned long long g_best[M_TOTAL * G_NUM];
__device__ int g_counts[G_NUM * V_NUM];

// ---------------------------------------------------------------------------
// Helpers
// ---------------------------------------------------------------------------
__device__ __forceinline__ uint32_t smem_u32(const void* p) {
    uint32_t a;
    asm("{ .reg .u64 t; cvta.to.shared.u64 t, %1; cvt.u32.u64 %0, t; }"
        : "=r"(a) : "l"(p));
    return a;
}

__device__ __forceinline__ void cp_async16(uint32_t dst, const void* src) {
    asm volatile("cp.async.cg.shared.global [%0], [%1], 16;"
                 :: "r"(dst), "l"(src) : "memory");
}

__device__ __forceinline__ void ldm_x4(uint32_t* r, uint32_t addr) {
    asm volatile("ldmatrix.sync.aligned.m8n8.x4.shared.b16 {%0,%1,%2,%3}, [%4];"
                 : "=r"(r[0]), "=r"(r[1]), "=r"(r[2]), "=r"(r[3]) : "r"(addr));
}

__device__ __forceinline__ void mma16(float* c, const uint32_t* a,
                                      uint32_t b0, uint32_t b1) {
    asm volatile(
        "mma.sync.aligned.m16n8k16.row.col.f32.f16.f16.f32 "
        "{%0,%1,%2,%3},{%4,%5,%6,%7},{%8,%9},{%0,%1,%2,%3};"
        : "+f"(c[0]), "+f"(c[1]), "+f"(c[2]), "+f"(c[3])
        : "r"(a[0]), "r"(a[1]), "r"(a[2]), "r"(a[3]), "r"(b0), "r"(b1));
}

__device__ __forceinline__ uint32_t ordf(float v) {
    uint32_t u = __float_as_uint(v);
    return (u & 0x80000000u) ? ~u : (u | 0x80000000u);
}

// split 2 floats -> packed h2 and m2 (h = rn16(x), m = rn16(x - h))
__device__ __forceinline__ void split2(float x0, float x1,
                                       uint32_t& hp, uint32_t& mp) {
    __half2 h2 = __floats2half2_rn(x0, x1);
    float2 hf = __half22float2(h2);
    __half2 m2 = __floats2half2_rn(x0 - hf.x, x1 - hf.y);
    hp = *reinterpret_cast<uint32_t*>(&h2);
    mp = *reinterpret_cast<uint32_t*>(&m2);
}

// ---------------------------------------------------------------------------
// Pre-pass: A fp32 -> fp16 (h, m) per 16-k block (vectorized loads)
// ---------------------------------------------------------------------------
__global__ void splitA_kernel(const float* __restrict__ A) {
    int id = blockIdx.x * blockDim.x + threadIdx.x;   // m*32 + kb
    if (id >= M_TOTAL * 32) return;
    const float4* src = (const float4*)(A + (size_t)id * 16);
    float4 v0 = src[0], v1 = src[1], v2 = src[2], v3 = src[3];
    uint32_t hp[8], mp[8];
    split2(v0.x, v0.y, hp[0], mp[0]);
    split2(v0.z, v0.w, hp[1], mp[1]);
    split2(v1.x, v1.y, hp[2], mp[2]);
    split2(v1.z, v1.w, hp[3], mp[3]);
    split2(v2.x, v2.y, hp[4], mp[4]);
    split2(v2.z, v2.w, hp[5], mp[5]);
    split2(v3.x, v3.y, hp[6], mp[6]);
    split2(v3.z, v3.w, hp[7], mp[7]);
    uint4* dst = g_asp + (size_t)id * 4;
    dst[0] = make_uint4(hp[0], hp[1], hp[2], hp[3]);
    dst[1] = make_uint4(hp[4], hp[5], hp[6], hp[7]);
    dst[2] = make_uint4(mp[0], mp[1], mp[2], mp[3]);
    dst[3] = make_uint4(mp[4], mp[5], mp[6], mp[7]);
}

// ---------------------------------------------------------------------------
// Pre-pass: init scratch + W[k][n]*64 -> fp16 (h, m) b-fragments, per-lane order
// ---------------------------------------------------------------------------
__global__ void splitB_init_kernel(const float* __restrict__ W) {
    int id = blockIdx.x * blockDim.x + threadIdx.x;   // 0 .. 81919
    if (id < M_TOTAL * G_NUM) g_best[id] = 0ull;
    if (id < G_NUM * V_NUM) g_counts[id] = 0;
    if (id >= 80 * 32 * 32) return;

    int l   = id & 31;
    int kb  = (id >> 5) & 31;
    int ntg = id >> 10;
    int k0  = kb * 16 + (l & 3) * 2;
    int n   = ntg * 8 + (l >> 2);

    float w0 = W[(size_t)(k0)     * N_DIM + n] * WSCALE;
    float w1 = W[(size_t)(k0 + 1) * N_DIM + n] * WSCALE;
    float w8 = W[(size_t)(k0 + 8) * N_DIM + n] * WSCALE;
    float w9 = W[(size_t)(k0 + 9) * N_DIM + n] * WSCALE;

    uint32_t h01, m01, h89, m89;
    split2(w0, w1, h01, m01);
    split2(w8, w9, h89, m89);
    g_bsp[id] = make_uint4(h01, h89, m01, m89);
}

// ---------------------------------------------------------------------------
// fp16 2-way split, 3-term (hh + hm + mh) GEMM.
// A: pre-split fp16, cp.async -> 3-buffer smem -> ldmatrix.x4 (ONE barrier
//    per stage: the pre-compute barrier at stage s proves all warps finished
//    compute(s-1), which read buffer (s-1)%3 == (s+2)%3 — the buffer that
//    loadA(s+2) overwrites).
// B: fragment-ordered gmem -> registers, prefetched one stage ahead
//    (latency hidden under previous stage's compute; L1-resident across the
//    4 co-resident CTAs sharing `by`).
// 128 threads, 4 warps 2(m) x 2(n), warp tile 32x32, 4 CTAs/SM.
// grid (512, 10). Fused bias + argmax epilogue.
// ---------------------------------------------------------------------------
__global__ __launch_bounds__(128, 4)
void gemm_fp16_kernel(const float* __restrict__ bias) {
    extern __shared__ char smem[];
    const uint32_t sb = smem_u32(smem);
    const int tid  = threadIdx.x;
    const int wid  = tid >> 5;
    const int lane = tid & 31;
    const int g    = lane >> 2;       // C row within 8
    const int t    = lane & 3;        // C col pair
    const int wm   = (wid & 1) * 32;
    const int wn   = (wid >> 1) * 32;
    const int bm   = blockIdx.x * BM;
    const int by   = blockIdx.y;
    const int bn   = by * BN;

    // ldmatrix row/chunk assignment for this lane
    const int lrow_off = ((lane >> 3) & 1) * 8 + (lane & 7);
    const int lkh      = lane >> 4;   // which 16B chunk of the k16

    // per-warp B fragment base: frag(nt, s, j) = Bg[nt*1024 + (s*2+j)*32]
    const uint4* Bg = g_bsp + (size_t)(by * 8 + (wn >> 3)) * 1024 + lane;

    float acc[2][4][4];
#pragma unroll
    for (int a = 0; a < 2; a++)
#pragma unroll
        for (int b = 0; b < 4; b++)
#pragma unroll
            for (int c = 0; c < 4; c++) acc[a][b][c] = 0.0f;

    uint4 b0[4][2], b1[4][2];

    auto loadB = [&](int s, uint4 (*bb)[2]) {
#pragma unroll
        for (int nt = 0; nt < 4; nt++)
#pragma unroll
            for (int j = 0; j < 2; j++)
                bb[nt][j] = __ldg(&Bg[(size_t)nt * 1024 + (s * 2 + j) * 32]);
    };

    auto loadA = [&](int s) {
        uint32_t Asm = sb + (s % NSTG) * A_ST;
        // A: 512 x 16B (pre-split fp16, 128B/row), XOR-swizzled 16B chunks
#pragma unroll
        for (int i = 0; i < 4; i++) {
            int c   = tid + i * 128;
            int row = c >> 3;
            int q   = c & 7;
            const char* src = (const char*)g_asp + (size_t)(bm + row) * 2048
                            + s * 128 + q * 16;
            cp_async16(Asm + row * 128 + ((q ^ (row & 7)) * 16), src);
        }
        asm volatile("cp.async.commit_group;" ::: "memory");
    };

    auto compute = [&](int s, uint4 (*bb)[2]) {
        uint32_t Asm = sb + (s % NSTG) * A_ST;
#pragma unroll
        for (int j = 0; j < 2; j++) {
            uint32_t ah[2][4], am[2][4];
#pragma unroll
            for (int mt = 0; mt < 2; mt++) {
                int row = wm + mt * 16 + lrow_off;
                uint32_t base = Asm + row * 128;
                uint32_t ch = ((j << 2) + lkh)     ^ (row & 7);
                uint32_t cm = ((j << 2) + 2 + lkh) ^ (row & 7);
                ldm_x4(ah[mt], base + ch * 16);
                ldm_x4(am[mt], base + cm * 16);
            }
#pragma unroll
            for (int nt = 0; nt < 4; nt++) {
#pragma unroll
                for (int mt = 0; mt < 2; mt++) {
                    mma16(acc[mt][nt], ah[mt], bb[nt][j].x, bb[nt][j].y);  // hh
                    mma16(acc[mt][nt], ah[mt], bb[nt][j].z, bb[nt][j].w);  // hm
                    mma16(acc[mt][nt], am[mt], bb[nt][j].x, bb[nt][j].y);  // mh
                }
            }
        }
    };

    // ---- pipeline: A triple-buffered cp.async (1 barrier/stage);
    //      B registers one stage ahead (alternating b0/b1)
    loadB(0, b0);
    loadA(0);
    loadA(1);
#pragma unroll 1
    for (int ss = 0; ss < NKS / 2; ss++) {
        int s0 = 2 * ss, s1 = s0 + 1;
        // ---- stage s0 (B in b0) ----
        loadB(s1, b1);
        if (s0 < NKS - 2)
            asm volatile("cp.async.wait_group 1;" ::: "memory");
        else
            asm volatile("cp.async.wait_group 0;" ::: "memory");
        __syncthreads();
        if (s0 + 2 < NKS) loadA(s0 + 2);
        compute(s0, b0);
        // ---- stage s1 (B in b1) ----
        if (s1 + 1 < NKS) loadB(s1 + 1, b0);
        if (s1 < NKS - 2)
            asm volatile("cp.async.wait_group 1;" ::: "memory");
        else
            asm volatile("cp.async.wait_group 0;" ::: "memory");
        __syncthreads();
        if (s1 + 2 < NKS) loadA(s1 + 2);
        compute(s1, b1);
    }

    // ---- fused epilogue: scaled bias + packed argmax + atomicMax ----
    const int gcol    = (bn >= V_NUM) ? 1 : 0;     // 64 | 320: whole CTA in one group
    const int colbase = bn + wn - gcol * V_NUM;

    unsigned long long best[4];    // [mt][half]
#pragma unroll
    for (int i = 0; i < 4; i++) best[i] = 0ull;

#pragma unroll
    for (int nt = 0; nt < 4; nt++) {
        int colg = colbase + nt * 8 + 2 * t;
        float bb0 = bias[bn + wn + nt * 8 + 2 * t]     * WSCALE;
        float bb1 = bias[bn + wn + nt * 8 + 2 * t + 1] * WSCALE;
#pragma unroll
        for (int mt = 0; mt < 2; mt++) {
            float v0 = acc[mt][nt][0] + bb0;
            float v1 = acc[mt][nt][1] + bb1;
            float v2 = acc[mt][nt][2] + bb0;
            float v3 = acc[mt][nt][3] + bb1;
            unsigned long long c0 = ((unsigned long long)ordf(v0) << 32) | (uint32_t)(~colg);
            unsigned long long c1 = ((unsigned long long)ordf(v1) << 32) | (uint32_t)(~(colg + 1));
            unsigned long long c2 = ((unsigned long long)ordf(v2) << 32) | (uint32_t)(~colg);
            unsigned long long c3 = ((unsigned long long)ordf(v3) << 32) | (uint32_t)(~(colg + 1));
            if (c0 > best[mt * 2])     best[mt * 2]     = c0;
            if (c1 > best[mt * 2])     best[mt * 2]     = c1;
            if (c2 > best[mt * 2 + 1]) best[mt * 2 + 1] = c2;
            if (c3 > best[mt * 2 + 1]) best[mt * 2 + 1] = c3;
        }
    }
#pragma unroll
    for (int i = 0; i < 4; i++) {
        unsigned long long o1 = __shfl_xor_sync(0xffffffffu, best[i], 1);
        if (o1 > best[i]) best[i] = o1;
        unsigned long long o2 = __shfl_xor_sync(0xffffffffu, best[i], 2);
        if (o2 > best[i]) best[i] = o2;
    }
    if (t == 0) {
#pragma unroll
        for (int mt = 0; mt < 2; mt++)
#pragma unroll
            for (int half = 0; half < 2; half++) {
                int row = bm + wm + mt * 16 + g + half * 8;
                atomicMax(&g_best[row * G_NUM + gcol], best[mt * 2 + half]);
            }
    }
}

// ---------------------------------------------------------------------------
// Finalize: decode packed best -> histogram + gather codevectors.
// Each warp handles FOUR (m,g) pairs: 4 independent load->gather->store
// chains give MLP=4 (the single-chain version was latency-bound).
// ---------------------------------------------------------------------------
__global__ void finalize_kernel(const float* __restrict__ cb,
                                float* __restrict__ out) {
    int warp = (blockIdx.x * blockDim.x + threadIdx.x) >> 5;
    int lane = threadIdx.x & 31;
    int w0 = warp * 4;
    if (w0 >= M_TOTAL * G_NUM) return;

    unsigned long long b[4];
    int col[4];
#pragma unroll
    for (int i = 0; i < 4; i++) b[i] = g_best[w0 + i];
#pragma unroll
    for (int i = 0; i < 4; i++) col[i] = (int)(~(uint32_t)b[i]);

    float4 v[4];
#pragma unroll
    for (int i = 0; i < 4; i++) {
        int g = (w0 + i) & 1;
        v[i] = __ldg((const float4*)(cb + (size_t)(g * V_NUM + col[i]) * DG + lane * 4));
    }
#pragma unroll
    for (int i = 0; i < 4; i++)
        __stcs((float4*)(out + (size_t)(w0 + i) * DG + lane * 4), v[i]);

    if (lane == 0) {
#pragma unroll
        for (int i = 0; i < 4; i++)
            atomicAdd(&g_counts[((w0 + i) & 1) * V_NUM + col[i]], 1);
    }
}

// ---------------------------------------------------------------------------
// Perplexity (parallel reduction)
// ---------------------------------------------------------------------------
__global__ void perp_kernel(float* __restrict__ out_p) {
    __shared__ float partial[G_NUM * V_NUM];
    __shared__ float pg[G_NUM];
    int t = threadIdx.x;
    if (t < G_NUM * V_NUM) {
        float m = (float)g_counts[t] * (1.0f / (float)M_TOTAL);
        partial[t] = m * logf(m + 1e-7f);
    }
    __syncthreads();
    if (t < 64) {
        int grp  = t >> 5;
        int lane = t & 31;
        float s = 0.0f;
#pragma unroll
        for (int i = 0; i < 10; i++) s += partial[grp * V_NUM + lane + i * 32];
#pragma unroll
        for (int off = 16; off > 0; off >>= 1)
            s += __shfl_down_sync(0xffffffffu, s, off);
        if (lane == 0) pg[grp] = expf(-s);
    }
    __syncthreads();
    if (t == 0) *out_p = pg[0] + pg[1];
}

// ---------------------------------------------------------------------------
// Launch
// ---------------------------------------------------------------------------
extern "C" void kernel_launch(void* const* d_in, const int* in_sizes, int n_in,
                              void* d_out, int out_size) {
    const float* hs = (const float*)d_in[0];   // (B,S,H)
    const float* W  = (const float*)d_in[1];   // (H, G*V)
    const float* b  = (const float*)d_in[2];   // (G*V,)
    const float* cb = (const float*)d_in[3];   // (1, G*V, Dg)
    float* out = (float*)d_out;

    cudaFuncSetAttribute(gemm_fp16_kernel,
                         cudaFuncAttributeMaxDynamicSharedMemorySize, SMEM_BYTES);

    splitB_init_kernel<<<(80 * 32 * 32 + 255) / 256, 256>>>(W);
    splitA_kernel<<<(M_TOTAL * 32 + 255) / 256, 256>>>(hs);

    dim3 grid(M_TOTAL / BM, N_DIM / BN);   // (512, 10)
    gemm_fp16_kernel<<<grid, 128, SMEM_BYTES>>>(b);

    int nwarp = M_TOTAL * G_NUM / 4;       // 16384 warps, 4 pairs each
    finalize_kernel<<<(nwarp * 32 + 255) / 256, 256>>>(cb, out);

    int n_out = M_TOTAL * G_NUM * DG;
    if (out_size > n_out) {
        perp_kernel<<<1, G_NUM * V_NUM>>>(out + n_out);
    }
}

// round 17
// speedup vs baseline: 1.0481x; 1.0481x over previous
#include <cuda_runtime.h>
#include <cuda_fp16.h>
#include <math.h>
#include <stdint.h>

// ---------------------------------------------------------------------------
// Problem constants
// ---------------------------------------------------------------------------
#define M_TOTAL 32768      // B*S
#define K_DIM   512        // H
#define N_DIM   640        // G*V
#define G_NUM   2
#define V_NUM   320
#define DG      128
#define WSCALE  64.0f      // pre-scale on W and bias (argmax-invariant)

// GEMM tiling: BM=BN=64, A through smem (2 buffers), B direct-to-register
#define BM 64
#define BN 64
#define BK 32
#define NKS (K_DIM / BK)        // 16 k-stages
#define A_ST 8192               // A stage bytes: 64 rows x 128B (fp16 h+m)
#define SMEM_BYTES (2 * A_ST)   // 16384 (x5 CTAs = 80KB/SM)

// ---------------------------------------------------------------------------
// Device-global scratch
// ---------------------------------------------------------------------------
__device__ uint4 g_asp[(size_t)M_TOTAL * 32 * 4];   // A split: per (m,kb16): h[32B] m[32B]
__device__ uint4 g_bsp[80 * 32 * 32];               // B split, frag-permuted: [ntg][kb][lane]
__device__ unsigned long long g_best[M_TOTAL * G_NUM];
__device__ int g_counts[G_NUM * V_NUM];

// ---------------------------------------------------------------------------
// Helpers
// ---------------------------------------------------------------------------
__device__ __forceinline__ uint32_t smem_u32(const void* p) {
    uint32_t a;
    asm("{ .reg .u64 t; cvta.to.shared.u64 t, %1; cvt.u32.u64 %0, t; }"
        : "=r"(a) : "l"(p));
    return a;
}

__device__ __forceinline__ void cp_async16(uint32_t dst, const void* src) {
    asm volatile("cp.async.cg.shared.global [%0], [%1], 16;"
                 :: "r"(dst), "l"(src) : "memory");
}

__device__ __forceinline__ void ldm_x4(uint32_t* r, uint32_t addr) {
    asm volatile("ldmatrix.sync.aligned.m8n8.x4.shared.b16 {%0,%1,%2,%3}, [%4];"
                 : "=r"(r[0]), "=r"(r[1]), "=r"(r[2]), "=r"(r[3]) : "r"(addr));
}

__device__ __forceinline__ void mma16(float* c, const uint32_t* a,
                                      uint32_t b0, uint32_t b1) {
    asm volatile(
        "mma.sync.aligned.m16n8k16.row.col.f32.f16.f16.f32 "
        "{%0,%1,%2,%3},{%4,%5,%6,%7},{%8,%9},{%0,%1,%2,%3};"
        : "+f"(c[0]), "+f"(c[1]), "+f"(c[2]), "+f"(c[3])
        : "r"(a[0]), "r"(a[1]), "r"(a[2]), "r"(a[3]), "r"(b0), "r"(b1));
}

__device__ __forceinline__ uint32_t ordf(float v) {
    uint32_t u = __float_as_uint(v);
    return (u & 0x80000000u) ? ~u : (u | 0x80000000u);
}

// split 2 floats -> packed h2 and m2 (h = rn16(x), m = rn16(x - h))
__device__ __forceinline__ void split2(float x0, float x1,
                                       uint32_t& hp, uint32_t& mp) {
    __half2 h2 = __floats2half2_rn(x0, x1);
    float2 hf = __half22float2(h2);
    __half2 m2 = __floats2half2_rn(x0 - hf.x, x1 - hf.y);
    hp = *reinterpret_cast<uint32_t*>(&h2);
    mp = *reinterpret_cast<uint32_t*>(&m2);
}

// ---------------------------------------------------------------------------
// Pre-pass: A fp32 -> fp16 (h, m) per 16-k block (vectorized loads)
// ---------------------------------------------------------------------------
__global__ void splitA_kernel(const float* __restrict__ A) {
    int id = blockIdx.x * blockDim.x + threadIdx.x;   // m*32 + kb
    if (id >= M_TOTAL * 32) return;
    const float4* src = (const float4*)(A + (size_t)id * 16);
    float4 v0 = src[0], v1 = src[1], v2 = src[2], v3 = src[3];
    uint32_t hp[8], mp[8];
    split2(v0.x, v0.y, hp[0], mp[0]);
    split2(v0.z, v0.w, hp[1], mp[1]);
    split2(v1.x, v1.y, hp[2], mp[2]);
    split2(v1.z, v1.w, hp[3], mp[3]);
    split2(v2.x, v2.y, hp[4], mp[4]);
    split2(v2.z, v2.w, hp[5], mp[5]);
    split2(v3.x, v3.y, hp[6], mp[6]);
    split2(v3.z, v3.w, hp[7], mp[7]);
    uint4* dst = g_asp + (size_t)id * 4;
    dst[0] = make_uint4(hp[0], hp[1], hp[2], hp[3]);
    dst[1] = make_uint4(hp[4], hp[5], hp[6], hp[7]);
    dst[2] = make_uint4(mp[0], mp[1], mp[2], mp[3]);
    dst[3] = make_uint4(mp[4], mp[5], mp[6], mp[7]);
}

// ---------------------------------------------------------------------------
// Pre-pass: init scratch + W[k][n]*64 -> fp16 (h, m) b-fragments, per-lane order
// ---------------------------------------------------------------------------
__global__ void splitB_init_kernel(const float* __restrict__ W) {
    int id = blockIdx.x * blockDim.x + threadIdx.x;   // 0 .. 81919
    if (id < M_TOTAL * G_NUM) g_best[id] = 0ull;
    if (id < G_NUM * V_NUM) g_counts[id] = 0;
    if (id >= 80 * 32 * 32) return;

    int l   = id & 31;
    int kb  = (id >> 5) & 31;
    int ntg = id >> 10;
    int k0  = kb * 16 + (l & 3) * 2;
    int n   = ntg * 8 + (l >> 2);

    float w0 = W[(size_t)(k0)     * N_DIM + n] * WSCALE;
    float w1 = W[(size_t)(k0 + 1) * N_DIM + n] * WSCALE;
    float w8 = W[(size_t)(k0 + 8) * N_DIM + n] * WSCALE;
    float w9 = W[(size_t)(k0 + 9) * N_DIM + n] * WSCALE;

    uint32_t h01, m01, h89, m89;
    split2(w0, w1, h01, m01);
    split2(w8, w9, h89, m89);
    g_bsp[id] = make_uint4(h01, h89, m01, m89);
}

// ---------------------------------------------------------------------------
// fp16 2-way split, 3-term (hh + hm + mh) GEMM.
// A: pre-split fp16 via cp.async -> 2-buffer smem -> ldmatrix.x4.
// B: fragment-ordered gmem -> registers, prefetched ONE J-PHASE (half-stage)
//    ahead in two 4xuint4 ping-pong buffers (32 regs instead of R15's 64),
//    which brings the kernel under the 96-reg cap for 5 CTAs/SM.
// 128 threads, 4 warps 2(m) x 2(n), warp tile 32x32, 5 CTAs/SM.
// grid (512, 10). Fused bias + argmax epilogue.
// ---------------------------------------------------------------------------
__global__ __launch_bounds__(128, 5)
void gemm_fp16_kernel(const float* __restrict__ bias) {
    extern __shared__ char smem[];
    const uint32_t sb = smem_u32(smem);
    const int tid  = threadIdx.x;
    const int wid  = tid >> 5;
    const int lane = tid & 31;
    const int g    = lane >> 2;       // C row within 8
    const int t    = lane & 3;        // C col pair
    const int wm   = (wid & 1) * 32;
    const int wn   = (wid >> 1) * 32;
    const int bm   = blockIdx.x * BM;
    const int by   = blockIdx.y;
    const int bn   = by * BN;

    // ldmatrix row/chunk assignment for this lane
    const int lrow_off = ((lane >> 3) & 1) * 8 + (lane & 7);
    const int lkh      = lane >> 4;   // which 16B chunk of the k16

    // per-warp B fragment base: frag(nt, phase) = Bg[nt*1024 + phase*32]
    const uint4* Bg = g_bsp + (size_t)(by * 8 + (wn >> 3)) * 1024 + lane;

    float acc[2][4][4];
#pragma unroll
    for (int a = 0; a < 2; a++)
#pragma unroll
        for (int b = 0; b < 4; b++)
#pragma unroll
            for (int c = 0; c < 4; c++) acc[a][b][c] = 0.0f;

    uint4 bA[4], bB[4];   // j-phase ping-pong B buffers (16+16 regs)

    auto loadBj = [&](int phase, uint4* bb) {
#pragma unroll
        for (int nt = 0; nt < 4; nt++)
            bb[nt] = __ldg(&Bg[(size_t)nt * 1024 + phase * 32]);
    };

    auto loadA = [&](int s) {
        uint32_t Asm = sb + (s & 1) * A_ST;
        // A: 512 x 16B (pre-split fp16, 128B/row), XOR-swizzled 16B chunks
#pragma unroll
        for (int i = 0; i < 4; i++) {
            int c   = tid + i * 128;
            int row = c >> 3;
            int q   = c & 7;
            const char* src = (const char*)g_asp + (size_t)(bm + row) * 2048
                            + s * 128 + q * 16;
            cp_async16(Asm + row * 128 + ((q ^ (row & 7)) * 16), src);
        }
        asm volatile("cp.async.commit_group;" ::: "memory");
    };

    // one j-phase of compute: ldmatrix A frags + 24 HMMAs against bb
    auto compute_j = [&](int s, int j, const uint4* bb) {
        uint32_t Asm = sb + (s & 1) * A_ST;
        uint32_t ah[2][4], am[2][4];
#pragma unroll
        for (int mt = 0; mt < 2; mt++) {
            int row = wm + mt * 16 + lrow_off;
            uint32_t base = Asm + row * 128;
            uint32_t ch = ((j << 2) + lkh)     ^ (row & 7);
            uint32_t cm = ((j << 2) + 2 + lkh) ^ (row & 7);
            ldm_x4(ah[mt], base + ch * 16);
            ldm_x4(am[mt], base + cm * 16);
        }
#pragma unroll
        for (int nt = 0; nt < 4; nt++) {
#pragma unroll
            for (int mt = 0; mt < 2; mt++) {
                mma16(acc[mt][nt], ah[mt], bb[nt].x, bb[nt].y);  // hh
                mma16(acc[mt][nt], ah[mt], bb[nt].z, bb[nt].w);  // hm
                mma16(acc[mt][nt], am[mt], bb[nt].x, bb[nt].y);  // mh
            }
        }
    };

    // ---- pipeline: A double-buffered cp.async; B one j-phase ahead ----
    loadBj(0, bA);
    loadA(0);
    loadA(1);
#pragma unroll 1
    for (int s = 0; s < NKS; s++) {
        if (s < NKS - 2)
            asm volatile("cp.async.wait_group 1;" ::: "memory");
        else
            asm volatile("cp.async.wait_group 0;" ::: "memory");
        __syncthreads();
        loadBj(2 * s + 1, bB);           // phase for j=1 of this stage
        compute_j(s, 0, bA);
        if (2 * s + 2 < 2 * NKS) loadBj(2 * s + 2, bA);   // j=0 of next stage
        compute_j(s, 1, bB);
        __syncthreads();
        if (s + 2 < NKS) loadA(s + 2);
    }

    // ---- fused epilogue: scaled bias + packed argmax + atomicMax ----
    const int gcol    = (bn >= V_NUM) ? 1 : 0;     // 64 | 320: whole CTA in one group
    const int colbase = bn + wn - gcol * V_NUM;

    unsigned long long best[4];    // [mt][half]
#pragma unroll
    for (int i = 0; i < 4; i++) best[i] = 0ull;

#pragma unroll
    for (int nt = 0; nt < 4; nt++) {
        int colg = colbase + nt * 8 + 2 * t;
        float bb0 = bias[bn + wn + nt * 8 + 2 * t]     * WSCALE;
        float bb1 = bias[bn + wn + nt * 8 + 2 * t + 1] * WSCALE;
#pragma unroll
        for (int mt = 0; mt < 2; mt++) {
            float v0 = acc[mt][nt][0] + bb0;
            float v1 = acc[mt][nt][1] + bb1;
            float v2 = acc[mt][nt][2] + bb0;
            float v3 = acc[mt][nt][3] + bb1;
            unsigned long long c0 = ((unsigned long long)ordf(v0) << 32) | (uint32_t)(~colg);
            unsigned long long c1 = ((unsigned long long)ordf(v1) << 32) | (uint32_t)(~(colg + 1));
            unsigned long long c2 = ((unsigned long long)ordf(v2) << 32) | (uint32_t)(~colg);
            unsigned long long c3 = ((unsigned long long)ordf(v3) << 32) | (uint32_t)(~(colg + 1));
            if (c0 > best[mt * 2])     best[mt * 2]     = c0;
            if (c1 > best[mt * 2])     best[mt * 2]     = c1;
            if (c2 > best[mt * 2 + 1]) best[mt * 2 + 1] = c2;
            if (c3 > best[mt * 2 + 1]) best[mt * 2 + 1] = c3;
        }
    }
#pragma unroll
    for (int i = 0; i < 4; i++) {
        unsigned long long o1 = __shfl_xor_sync(0xffffffffu, best[i], 1);
        if (o1 > best[i]) best[i] = o1;
        unsigned long long o2 = __shfl_xor_sync(0xffffffffu, best[i], 2);
        if (o2 > best[i]) best[i] = o2;
    }
    if (t == 0) {
#pragma unroll
        for (int mt = 0; mt < 2; mt++)
#pragma unroll
            for (int half = 0; half < 2; half++) {
                int row = bm + wm + mt * 16 + g + half * 8;
                atomicMax(&g_best[row * G_NUM + gcol], best[mt * 2 + half]);
            }
    }
}

// ---------------------------------------------------------------------------
// Finalize: decode packed best -> histogram + gather codevectors.
// One warp per (m, g); streaming stores for the 32MB output. (R15 version —
// the MLP-4 variant measured slower.)
// ---------------------------------------------------------------------------
__global__ void finalize_kernel(const float* __restrict__ cb,
                                float* __restrict__ out) {
    int w    = (blockIdx.x * blockDim.x + threadIdx.x) >> 5;   // (m,g) index
    int lane = threadIdx.x & 31;
    if (w >= M_TOTAL * G_NUM) return;
    int g = w & 1;
    unsigned long long b = g_best[w];          // broadcast load
    int col = (int)(~(uint32_t)b);
    if (lane == 0) atomicAdd(&g_counts[g * V_NUM + col], 1);
    float4 v = __ldg((const float4*)(cb + (size_t)(g * V_NUM + col) * DG + lane * 4));
    __stcs((float4*)(out + (size_t)w * DG + lane * 4), v);
}

// ---------------------------------------------------------------------------
// Perplexity (parallel reduction)
// ---------------------------------------------------------------------------
__global__ void perp_kernel(float* __restrict__ out_p) {
    __shared__ float partial[G_NUM * V_NUM];
    __shared__ float pg[G_NUM];
    int t = threadIdx.x;
    if (t < G_NUM * V_NUM) {
        float m = (float)g_counts[t] * (1.0f / (float)M_TOTAL);
        partial[t] = m * logf(m + 1e-7f);
    }
    __syncthreads();
    if (t < 64) {
        int grp  = t >> 5;
        int lane = t & 31;
        float s = 0.0f;
#pragma unroll
        for (int i = 0; i < 10; i++) s += partial[grp * V_NUM + lane + i * 32];
#pragma unroll
        for (int off = 16; off > 0; off >>= 1)
            s += __shfl_down_sync(0xffffffffu, s, off);
        if (lane == 0) pg[grp] = expf(-s);
    }
    __syncthreads();
    if (t == 0) *out_p = pg[0] + pg[1];
}

// ---------------------------------------------------------------------------
// Launch
// ---------------------------------------------------------------------------
extern "C" void kernel_launch(void* const* d_in, const int* in_sizes, int n_in,
                              void* d_out, int out_size) {
    const float* hs = (const float*)d_in[0];   // (B,S,H)
    const float* W  = (const float*)d_in[1];   // (H, G*V)
    const float* b  = (const float*)d_in[2];   // (G*V,)
    const float* cb = (const float*)d_in[3];   // (1, G*V, Dg)
    float* out = (float*)d_out;

    cudaFuncSetAttribute(gemm_fp16_kernel,
                         cudaFuncAttributeMaxDynamicSharedMemorySize, SMEM_BYTES);

    splitB_init_kernel<<<(80 * 32 * 32 + 255) / 256, 256>>>(W);
    splitA_kernel<<<(M_TOTAL * 32 + 255) / 256, 256>>>(hs);

    dim3 grid(M_TOTAL / BM, N_DIM / BN);   // (512, 10)
    gemm_fp16_kernel<<<grid, 128, SMEM_BYTES>>>(b);

    int warps = M_TOTAL * G_NUM;           // 65536 (m,g) pairs
    finalize_kernel<<<(warps * 32 + 255) / 256, 256>>>(cb, out);

    int n_out = M_TOTAL * G_NUM * DG;
    if (out_size > n_out) {
        perp_kernel<<<1, G_NUM * V_NUM>>>(out + n_out);
    }
}